// round 15
// baseline (speedup 1.0000x reference)
#include <cuda_runtime.h>
#include <cuda_bf16.h>
#include <cstdint>

// Problem constants
static constexpr int BB = 32;    // batch
static constexpr int TT = 512;   // time
static constexpr int HH = 1024;  // hidden
static constexpr int GG = 4096;  // 4*H gate columns (order i,f,g,o)
static constexpr int NL = 2;     // layers

static constexpr int NBLK = 128; // persistent blocks for recurrence
static constexpr int NTHR = 256;

// ---------------------------------------------------------------------------
// Device scratch
// ---------------------------------------------------------------------------
__device__ float g_zx[(size_t)TT * GG * BB];   // [t][c][b] input-GEMM result
__device__ float g_y0[(size_t)TT * HH * BB];   // layer-0 h, [t][u][b]
__device__ unsigned g_bar;                     // grid barrier counter

// recurrent h as split bf16, [parity][b][u]  (the layout the MMA A-tile wants)
__device__ __align__(16) __nv_bfloat16 g_hh[2][BB * HH];
__device__ __align__(16) __nv_bfloat16 g_hl[2][BB * HH];

// bf16 split operands for MMA GEMM phases
__device__ __align__(16) __nv_bfloat16 g_xh[(size_t)BB * TT * HH];   // [b][t][k]
__device__ __align__(16) __nv_bfloat16 g_xl[(size_t)BB * TT * HH];
__device__ __align__(16) __nv_bfloat16 g_y0h[(size_t)TT * BB * HH];  // [(t,b)][k]
__device__ __align__(16) __nv_bfloat16 g_y0l[(size_t)TT * BB * HH];
__device__ __align__(16) __nv_bfloat16 g_wth[(size_t)NL * GG * HH];  // Wx^T [l][c][k]
__device__ __align__(16) __nv_bfloat16 g_wtl[(size_t)NL * GG * HH];
// Wh^T split, block-permuted: row cl' = blk*32 + g*8 + uu  (c = g*1024+blk*8+uu)
// GG = 4096 rows per layer
__device__ __align__(16) __nv_bfloat16 g_rhh[(size_t)NL * GG * HH];
__device__ __align__(16) __nv_bfloat16 g_rhl[(size_t)NL * GG * HH];

// ---------------------------------------------------------------------------
// Helpers (all baseline PTX; no sm_103a-only instructions)
// ---------------------------------------------------------------------------
__device__ __forceinline__ uint32_t smem_to_u32(const void* p) {
    uint32_t a;
    asm("{ .reg .u64 t; cvta.to.shared.u64 t, %1; cvt.u32.u64 %0, t; }"
        : "=r"(a) : "l"(p));
    return a;
}

#define LDSM_X4(r0, r1, r2, r3, a) \
    asm volatile("ldmatrix.sync.aligned.m8n8.x4.shared.b16 {%0,%1,%2,%3}, [%4];" \
                 : "=r"(r0), "=r"(r1), "=r"(r2), "=r"(r3) : "r"(a))

#define MMA16816(d, a0, a1, a2, a3, b0, b1) \
    asm volatile("mma.sync.aligned.m16n8k16.row.col.f32.bf16.bf16.f32 " \
                 "{%0,%1,%2,%3}, {%4,%5,%6,%7}, {%8,%9}, {%0,%1,%2,%3};" \
                 : "+f"((d)[0]), "+f"((d)[1]), "+f"((d)[2]), "+f"((d)[3]) \
                 : "r"(a0), "r"(a1), "r"(a2), "r"(a3), "r"(b0), "r"(b1))

__device__ __forceinline__ void bf16split(float v, __nv_bfloat16& hi, __nv_bfloat16& lo) {
    hi = __float2bfloat16(v);
    lo = __float2bfloat16(v - __bfloat162float(hi));
}
__device__ __forceinline__ float sigmoidf_(float x) {
    return 1.0f / (1.0f + __expf(-x));
}

// ---------------------------------------------------------------------------
// Reset recurrent state + barrier counter
// ---------------------------------------------------------------------------
__global__ void zero_state() {
    int i = blockIdx.x * blockDim.x + threadIdx.x;
    if (i == 0) g_bar = 0u;
    if (i < BB * HH) {
        __nv_bfloat16 z = __float2bfloat16(0.0f);
        g_hh[0][i] = z; g_hh[1][i] = z;
        g_hl[0][i] = z; g_hl[1][i] = z;
    }
}

// ---------------------------------------------------------------------------
// Prep: Wx[l][k][c] fp32 -> Wx^T hi/lo bf16 [l][c][k]  (32x32 smem transpose)
// ---------------------------------------------------------------------------
__global__ __launch_bounds__(256) void conv_w(const float* __restrict__ Wx) {
    __shared__ float tile[32][33];
    const int l = blockIdx.z, c0 = blockIdx.x * 32, k0 = blockIdx.y * 32;
    const int tx = threadIdx.x & 31, ty = threadIdx.x >> 5;
    const float* W = Wx + (size_t)l * HH * GG;
#pragma unroll
    for (int i = 0; i < 4; i++)
        tile[ty + i * 8][tx] = W[(size_t)(k0 + ty + i * 8) * GG + c0 + tx];
    __syncthreads();
#pragma unroll
    for (int i = 0; i < 4; i++) {
        int c = ty + i * 8;
        __nv_bfloat16 hi, lo;
        bf16split(tile[tx][c], hi, lo);
        size_t off = (size_t)l * GG * HH + (size_t)(c0 + c) * HH + k0 + tx;
        g_wth[off] = hi;
        g_wtl[off] = lo;
    }
}

// ---------------------------------------------------------------------------
// Prep: Wh[l][k][c] fp32 -> Wh^T hi/lo bf16 with block-permuted rows:
//   c = g*1024 + blk*8 + uu  ->  row cl' = blk*32 + g*8 + uu   (4096 rows/layer)
// ---------------------------------------------------------------------------
__global__ __launch_bounds__(256) void conv_wh(const float* __restrict__ Wh) {
    __shared__ float tile[32][33];
    const int l = blockIdx.z, c0 = blockIdx.x * 32, k0 = blockIdx.y * 32;
    const int tx = threadIdx.x & 31, ty = threadIdx.x >> 5;
    const float* W = Wh + (size_t)l * HH * GG;
#pragma unroll
    for (int i = 0; i < 4; i++)
        tile[ty + i * 8][tx] = W[(size_t)(k0 + ty + i * 8) * GG + c0 + tx];
    __syncthreads();
#pragma unroll
    for (int i = 0; i < 4; i++) {
        int c = ty + i * 8;
        int cg = c0 + c;
        int g  = cg >> 10, r = cg & 1023;
        int clp = (r >> 3) * 32 + g * 8 + (r & 7);
        __nv_bfloat16 hi, lo;
        bf16split(tile[tx][c], hi, lo);
        size_t off = (size_t)l * GG * HH + (size_t)clp * HH + k0 + tx;
        g_rhh[off] = hi;
        g_rhl[off] = lo;
    }
}

// ---------------------------------------------------------------------------
// Prep: x fp32 [b][t][k] -> g_xh/g_xl bf16 same layout
// ---------------------------------------------------------------------------
__global__ __launch_bounds__(256) void conv_x(const float* __restrict__ x) {
    size_t i = ((size_t)blockIdx.x * 256 + threadIdx.x) * 4;
    float4 v = *reinterpret_cast<const float4*>(x + i);
    __nv_bfloat16 h[4], l[4];
    bf16split(v.x, h[0], l[0]); bf16split(v.y, h[1], l[1]);
    bf16split(v.z, h[2], l[2]); bf16split(v.w, h[3], l[3]);
    uint2 hw, lw;
    hw.x = (unsigned)__bfloat16_as_ushort(h[0]) | ((unsigned)__bfloat16_as_ushort(h[1]) << 16);
    hw.y = (unsigned)__bfloat16_as_ushort(h[2]) | ((unsigned)__bfloat16_as_ushort(h[3]) << 16);
    lw.x = (unsigned)__bfloat16_as_ushort(l[0]) | ((unsigned)__bfloat16_as_ushort(l[1]) << 16);
    lw.y = (unsigned)__bfloat16_as_ushort(l[2]) | ((unsigned)__bfloat16_as_ushort(l[3]) << 16);
    *reinterpret_cast<uint2*>(&g_xh[i]) = hw;
    *reinterpret_cast<uint2*>(&g_xl[i]) = lw;
}

// ---------------------------------------------------------------------------
// Prep: g_y0 fp32 [t][u][b] -> g_y0h/l bf16 [(t*32+b)][u]
// ---------------------------------------------------------------------------
__global__ __launch_bounds__(256) void conv_y0() {
    __shared__ float s[128][33];
    const int t = blockIdx.x, u0 = blockIdx.y * 128;
    const int lane = threadIdx.x & 31, w = threadIdx.x >> 5;
#pragma unroll
    for (int i = 0; i < 16; i++) {
        int uu = w + i * 8;
        s[uu][lane] = g_y0[((size_t)t * HH + u0 + uu) * BB + lane];
    }
    __syncthreads();
#pragma unroll
    for (int j = 0; j < 4; j++) {
        int b = w + j * 8;
        size_t base = ((size_t)(t * BB + b)) * HH + u0;
#pragma unroll
        for (int i = 0; i < 4; i++) {
            int uu = lane + i * 32;
            __nv_bfloat16 hi, lo;
            bf16split(s[uu][b], hi, lo);
            g_y0h[base + uu] = hi;
            g_y0l[base + uu] = lo;
        }
    }
}

// ---------------------------------------------------------------------------
// MMA GEMM (unchanged from passing R11): Zx = A @ Wx + bias, split-bf16
// ---------------------------------------------------------------------------
template <int LAYER>
__global__ __launch_bounds__(256) void gemm_mma(const float* __restrict__ bias) {
    __shared__ __align__(16) __nv_bfloat16 Ah_s[128 * 40];
    __shared__ __align__(16) __nv_bfloat16 Al_s[128 * 40];
    __shared__ __align__(16) __nv_bfloat16 Bh_s[128 * 40];
    __shared__ __align__(16) __nv_bfloat16 Bl_s[128 * 40];

    const int tid  = threadIdx.x;
    const int wid  = tid >> 5;
    const int lane = tid & 31;
    const int wm   = wid & 3;
    const int wn   = wid >> 2;
    const int n0   = blockIdx.x * 128;
    const int t0   = blockIdx.y * 4;

    int srow[2], sseg[2];
    unsigned arow[2], brow[2];
#pragma unroll
    for (int i = 0; i < 2; i++) {
        int e   = tid + i * 256;
        srow[i] = e >> 2;
        sseg[i] = e & 3;
        if (LAYER == 0) {
            int b = srow[i] & 31, t = t0 + (srow[i] >> 5);
            arow[i] = (unsigned)(b * TT + t) * HH;
        } else {
            arow[i] = (unsigned)(blockIdx.y * 128 + srow[i]) * HH;
        }
        brow[i] = (unsigned)(n0 + srow[i]) * HH;
    }
    const __nv_bfloat16* Ah = (LAYER == 0) ? g_xh : g_y0h;
    const __nv_bfloat16* Al = (LAYER == 0) ? g_xl : g_y0l;
    const __nv_bfloat16* Bh = g_wth + (size_t)LAYER * GG * HH;
    const __nv_bfloat16* Bl = g_wtl + (size_t)LAYER * GG * HH;

    const int a_lr = lane & 15;
    const int a_lc = (lane & 16) ? 8 : 0;
    const int b_lr = (lane & 7) + ((lane & 16) ? 8 : 0);
    const int b_lc = (lane & 8) ? 8 : 0;

    const uint32_t uAh = smem_to_u32(Ah_s), uAl = smem_to_u32(Al_s);
    const uint32_t uBh = smem_to_u32(Bh_s), uBl = smem_to_u32(Bl_s);

    float acc[2][8][4];
#pragma unroll
    for (int fm = 0; fm < 2; fm++)
#pragma unroll
        for (int nf = 0; nf < 8; nf++)
#pragma unroll
            for (int q = 0; q < 4; q++) acc[fm][nf][q] = 0.0f;

    for (int ch = 0; ch < 32; ch++) {
        const int k0 = ch * 32;
#pragma unroll
        for (int i = 0; i < 2; i++) {
            const unsigned go = k0 + sseg[i] * 8;
            const unsigned so = srow[i] * 40 + sseg[i] * 8;
            *reinterpret_cast<uint4*>(Ah_s + so) =
                *reinterpret_cast<const uint4*>(Ah + arow[i] + go);
            *reinterpret_cast<uint4*>(Al_s + so) =
                *reinterpret_cast<const uint4*>(Al + arow[i] + go);
            *reinterpret_cast<uint4*>(Bh_s + so) =
                *reinterpret_cast<const uint4*>(Bh + brow[i] + go);
            *reinterpret_cast<uint4*>(Bl_s + so) =
                *reinterpret_cast<const uint4*>(Bl + brow[i] + go);
        }
        __syncthreads();

#pragma unroll
        for (int ks = 0; ks < 2; ks++) {
            uint32_t ah[2][4], al[2][4];
#pragma unroll
            for (int fm = 0; fm < 2; fm++) {
                uint32_t off = (uint32_t)((wm * 32 + fm * 16 + a_lr) * 40 +
                                          ks * 16 + a_lc) * 2;
                LDSM_X4(ah[fm][0], ah[fm][1], ah[fm][2], ah[fm][3], uAh + off);
                LDSM_X4(al[fm][0], al[fm][1], al[fm][2], al[fm][3], uAl + off);
            }
#pragma unroll
            for (int ng = 0; ng < 4; ng++) {
                uint32_t off = (uint32_t)((wn * 64 + ng * 16 + b_lr) * 40 +
                                          ks * 16 + b_lc) * 2;
                uint32_t bh0, bh1, bh2, bh3, bl0, bl1, bl2, bl3;
                LDSM_X4(bh0, bh1, bh2, bh3, uBh + off);
                LDSM_X4(bl0, bl1, bl2, bl3, uBl + off);
                const int nf0 = ng * 2, nf1 = ng * 2 + 1;
#pragma unroll
                for (int fm = 0; fm < 2; fm++) {
                    MMA16816(acc[fm][nf0], ah[fm][0], ah[fm][1], ah[fm][2], ah[fm][3], bh0, bh1);
                    MMA16816(acc[fm][nf1], ah[fm][0], ah[fm][1], ah[fm][2], ah[fm][3], bh2, bh3);
                    MMA16816(acc[fm][nf0], ah[fm][0], ah[fm][1], ah[fm][2], ah[fm][3], bl0, bl1);
                    MMA16816(acc[fm][nf1], ah[fm][0], ah[fm][1], ah[fm][2], ah[fm][3], bl2, bl3);
                    MMA16816(acc[fm][nf0], al[fm][0], al[fm][1], al[fm][2], al[fm][3], bh0, bh1);
                    MMA16816(acc[fm][nf1], al[fm][0], al[fm][1], al[fm][2], al[fm][3], bh2, bh3);
                }
            }
        }
        __syncthreads();
    }

    const int er = lane >> 2, ec = (lane & 3) * 2;
#pragma unroll
    for (int fm = 0; fm < 2; fm++) {
#pragma unroll
        for (int nf = 0; nf < 8; nf++) {
            const int c0 = n0 + wn * 64 + nf * 8 + ec;
            const float bv0 = __ldg(&bias[c0]), bv1 = __ldg(&bias[c0 + 1]);
#pragma unroll
            for (int h = 0; h < 2; h++) {
                const int r = wm * 32 + fm * 16 + er + h * 8;
                const int t = t0 + (r >> 5), b = r & 31;
                const size_t base = ((size_t)t * GG + c0) * BB + b;
                __stcs(&g_zx[base],       acc[fm][nf][h * 2 + 0] + bv0);
                __stcs(&g_zx[base + BB],  acc[fm][nf][h * 2 + 1] + bv1);
            }
        }
    }
}

// ---------------------------------------------------------------------------
// Persistent recurrence with tensor-core mainloop.
//
// 128 blocks (8 units each -> 32 gate-cols cl = g*8+uu), 8 warps = 8-way
// K-split (128 k each). Wh^T split bf16 resident in smem (loaded once).
// Per step: each warp computes partial D[32 b][32 cl] over its k-chunk via
// mma.sync m16n8k16 (3-pass split-bf16), A (h) staged per 32-k sub-chunk
// from g_hh/g_hl[parity][b][u] with register-relay prefetch. Partials are
// reduced through padded smem Pz; fused gate epilogue publishes h as split
// bf16 (+fp32 y). Split-arrive grid barrier per step.
//
// smem map: Bh[32][1032] 66048 | Bl[32][1032] 66048 |
//           A: 8 warps x (Ah[32][40] 2560 + Al[32][40] 2560) = 40960 |
//           Pz: 8 x 1056 fp32 = 33792.  Total 206848 B.
// ---------------------------------------------------------------------------
static constexpr int SEQ_BH = 0;
static constexpr int SEQ_BL = 66048;
static constexpr int SEQ_A  = 132096;
static constexpr int SEQ_PZ = 132096 + 40960;          // 173056
static constexpr int SMEM_SEQ2 = SEQ_PZ + 33792;       // 206848 B

template <int LAYER>
__global__ __launch_bounds__(NTHR, 1) void lstm_seq(float* __restrict__ yout,
                                                    float* __restrict__ hfin,
                                                    float* __restrict__ cfin) {
    extern __shared__ char sm[];
    __nv_bfloat16* Bh_s = reinterpret_cast<__nv_bfloat16*>(sm + SEQ_BH);
    __nv_bfloat16* Bl_s = reinterpret_cast<__nv_bfloat16*>(sm + SEQ_BL);
    float*         Pz   = reinterpret_cast<float*>(sm + SEQ_PZ);

    const int blk  = blockIdx.x;
    const int u0   = blk * 8;
    const int tid  = threadIdx.x;
    const int ks   = tid >> 5;            // warp = K-split index
    const int lane = tid & 31;

    // warp-private A tiles: 5120 B per warp (Ah 2560 + Al 2560)
    __nv_bfloat16* Ah_w = reinterpret_cast<__nv_bfloat16*>(sm + SEQ_A + ks * 5120);
    __nv_bfloat16* Al_w = reinterpret_cast<__nv_bfloat16*>(sm + SEQ_A + ks * 5120 + 2560);

    // ---- one-time: load resident Wh^T split slice [32 cl'][1024 k] ----
    {
        const __nv_bfloat16* srcH = g_rhh + (size_t)LAYER * GG * HH + (size_t)blk * 32 * HH;
        const __nv_bfloat16* srcL = g_rhl + (size_t)LAYER * GG * HH + (size_t)blk * 32 * HH;
        for (int idx = tid; idx < 4096; idx += NTHR) {   // 32 rows x 128 uint4
            int row = idx >> 7, kq = idx & 127;
            *reinterpret_cast<uint4*>(Bh_s + row * 1032 + kq * 8) =
                *reinterpret_cast<const uint4*>(srcH + row * HH + kq * 8);
            *reinterpret_cast<uint4*>(Bl_s + row * 1032 + kq * 8) =
                *reinterpret_cast<const uint4*>(srcL + row * HH + kq * 8);
        }
    }
    __syncthreads();

    // fragment lane addressing (identical to gemm_mma)
    const int a_lr = lane & 15;
    const int a_lc = (lane & 16) ? 8 : 0;
    const int b_lr = (lane & 7) + ((lane & 16) ? 8 : 0);
    const int b_lc = (lane & 8) ? 8 : 0;
    const int er = lane >> 2, ec = (lane & 3) * 2;

    const uint32_t uAh = smem_to_u32(Ah_w), uAl = smem_to_u32(Al_w);
    const uint32_t uBh = smem_to_u32(Bh_s), uBl = smem_to_u32(Bl_s);

    // epilogue identity + register-resident c
    const int uu = ks;
    const int b  = lane;
    const int u  = u0 + uu;
    float c_reg = 0.0f;

    const int kbeg = ks * 128;

    for (int t = 0; t < TT; t++) {
        const int pin = t & 1, pout = (t + 1) & 1;

        // Zx addends: independent of h, hide DRAM latency under mainloop
        float zadd[4];
#pragma unroll
        for (int g = 0; g < 4; g++)
            zadd[g] = __ldcs(&g_zx[((size_t)t * GG + g * HH + u) * BB + b]);

        float acc[2][4][4];
#pragma unroll
        for (int fm = 0; fm < 2; fm++)
#pragma unroll
            for (int nf = 0; nf < 4; nf++)
#pragma unroll
                for (int q = 0; q < 4; q++) acc[fm][nf][q] = 0.0f;

        // A staging: lane owns batch row b=lane; sub-chunks of 32 k.
        const __nv_bfloat16* hhrow = g_hh[pin] + lane * HH + kbeg;
        const __nv_bfloat16* hlrow = g_hl[pin] + lane * HH + kbeg;

        // prologue: prefetch sub-chunk 0 (4 uint4 hi + 4 lo)
        uint4 pH[4], pL[4];
#pragma unroll
        for (int q = 0; q < 4; q++) {
            pH[q] = __ldcg(reinterpret_cast<const uint4*>(hhrow) + q);
            pL[q] = __ldcg(reinterpret_cast<const uint4*>(hlrow) + q);
        }

#pragma unroll
        for (int s = 0; s < 4; s++) {
            // commit prefetched sub-chunk to warp-private tile
#pragma unroll
            for (int q = 0; q < 4; q++) {
                *reinterpret_cast<uint4*>(Ah_w + lane * 40 + q * 8) = pH[q];
                *reinterpret_cast<uint4*>(Al_w + lane * 40 + q * 8) = pL[q];
            }
            __syncwarp();
            // prefetch next sub-chunk while computing this one
            if (s < 3) {
#pragma unroll
                for (int q = 0; q < 4; q++) {
                    pH[q] = __ldcg(reinterpret_cast<const uint4*>(hhrow + (s + 1) * 32) + q);
                    pL[q] = __ldcg(reinterpret_cast<const uint4*>(hlrow + (s + 1) * 32) + q);
                }
            }

#pragma unroll
            for (int kst = 0; kst < 2; kst++) {
                uint32_t ah[2][4], al[2][4];
#pragma unroll
                for (int fm = 0; fm < 2; fm++) {
                    uint32_t off = (uint32_t)((fm * 16 + a_lr) * 40 + kst * 16 + a_lc) * 2;
                    LDSM_X4(ah[fm][0], ah[fm][1], ah[fm][2], ah[fm][3], uAh + off);
                    LDSM_X4(al[fm][0], al[fm][1], al[fm][2], al[fm][3], uAl + off);
                }
                const int kgl = kbeg + s * 32 + kst * 16;
#pragma unroll
                for (int ng = 0; ng < 2; ng++) {
                    uint32_t off = (uint32_t)((ng * 16 + b_lr) * 1032 + kgl + b_lc) * 2;
                    uint32_t bh0, bh1, bh2, bh3, bl0, bl1, bl2, bl3;
                    LDSM_X4(bh0, bh1, bh2, bh3, uBh + off);
                    LDSM_X4(bl0, bl1, bl2, bl3, uBl + off);
                    const int nf0 = ng * 2, nf1 = ng * 2 + 1;
#pragma unroll
                    for (int fm = 0; fm < 2; fm++) {
                        MMA16816(acc[fm][nf0], ah[fm][0], ah[fm][1], ah[fm][2], ah[fm][3], bh0, bh1);
                        MMA16816(acc[fm][nf1], ah[fm][0], ah[fm][1], ah[fm][2], ah[fm][3], bh2, bh3);
                        MMA16816(acc[fm][nf0], ah[fm][0], ah[fm][1], ah[fm][2], ah[fm][3], bl0, bl1);
                        MMA16816(acc[fm][nf1], ah[fm][0], ah[fm][1], ah[fm][2], ah[fm][3], bl2, bl3);
                        MMA16816(acc[fm][nf0], al[fm][0], al[fm][1], al[fm][2], al[fm][3], bh0, bh1);
                        MMA16816(acc[fm][nf1], al[fm][0], al[fm][1], al[fm][2], al[fm][3], bh2, bh3);
                    }
                }
            }
            __syncwarp();
        }

        // dump partials: Pz[ks][cl][b], rows padded to 33
        {
            float* P = Pz + ks * 1056;
#pragma unroll
            for (int fm = 0; fm < 2; fm++)
#pragma unroll
                for (int nf = 0; nf < 4; nf++) {
                    const int bb = fm * 16 + er;
                    const int cl = nf * 8 + ec;
                    P[cl * 33 + bb]           = acc[fm][nf][0];
                    P[(cl + 1) * 33 + bb]     = acc[fm][nf][1];
                    P[cl * 33 + bb + 8]       = acc[fm][nf][2];
                    P[(cl + 1) * 33 + bb + 8] = acc[fm][nf][3];
                }
        }
        __syncthreads();

        // fused gate epilogue: thread -> (uu, b)
        float h_new;
        {
            float z[4];
#pragma unroll
            for (int g = 0; g < 4; g++) {
                const int cl = g * 8 + uu;
                float s = zadd[g];
#pragma unroll
                for (int w = 0; w < 8; w++) s += Pz[w * 1056 + cl * 33 + b];
                z[g] = s;
            }
            float gi = sigmoidf_(z[0]);
            float gf = sigmoidf_(z[1]);
            float gc = tanhf(z[2]);
            float go = sigmoidf_(z[3]);
            c_reg = gf * c_reg + gi * gc;
            h_new = go * tanhf(c_reg);

            // publish h as split bf16 in [b][u] layout (the MMA A layout)
            __nv_bfloat16 hi, lo;
            bf16split(h_new, hi, lo);
            g_hh[pout][b * HH + u] = hi;
            g_hl[pout][b * HH + u] = lo;
        }

        // --- split-arrive grid barrier ---
        __threadfence();
        __syncthreads();
        if (tid == 0) atomicAdd(&g_bar, 1u);

        // y-output stores overlap other blocks' arrival skew
        if (LAYER == 0) {
            __stcs(&g_y0[((size_t)t * HH + u) * BB + b], h_new);  // [t][u][b]
        } else {
            __stcs(&yout[((size_t)b * TT + t) * HH + u], h_new);  // [b][t][u]
        }
        if (t == TT - 1) {
            hfin[b * HH + u] = h_new;
            cfin[b * HH + u] = c_reg;
        }

        if (tid == 0) {
            const unsigned target = (unsigned)(t + 1) * (unsigned)NBLK;
            while (*((volatile unsigned*)&g_bar) < target) { }
            __threadfence();
        }
        __syncthreads();
    }
}

// ---------------------------------------------------------------------------
// Host launcher (graph-capturable: 10 kernel launches)
// ---------------------------------------------------------------------------
extern "C" void kernel_launch(void* const* d_in, const int* in_sizes, int n_in,
                              void* d_out, int out_size) {
    const float* x    = (const float*)d_in[0];   // [B,T,H]
    const float* Wx   = (const float*)d_in[1];   // [L,H,4H]
    const float* Wh   = (const float*)d_in[2];   // [L,H,4H]
    const float* bias = (const float*)d_in[3];   // [L,4H]

    float* out = (float*)d_out;
    float* y   = out;                               // [B,T,H]
    float* hf  = out + (size_t)BB * TT * HH;        // [L,B,H]
    float* cf  = hf + (size_t)NL * BB * HH;         // [L,B,H]

    cudaFuncSetAttribute(lstm_seq<0>, cudaFuncAttributeMaxDynamicSharedMemorySize, SMEM_SEQ2);
    cudaFuncSetAttribute(lstm_seq<1>, cudaFuncAttributeMaxDynamicSharedMemorySize, SMEM_SEQ2);

    // ---- Layer 0 ----
    zero_state<<<128, 256>>>();
    conv_w<<<dim3(GG / 32, HH / 32, NL), 256>>>(Wx);
    conv_wh<<<dim3(GG / 32, HH / 32, NL), 256>>>(Wh);
    conv_x<<<16384, 256>>>(x);
    gemm_mma<0><<<dim3(32, 128), 256>>>(bias);
    lstm_seq<0><<<NBLK, NTHR, SMEM_SEQ2>>>(nullptr, hf, cf);

    // ---- Layer 1 ----
    zero_state<<<128, 256>>>();
    conv_y0<<<dim3(TT, 8), 256>>>();
    gemm_mma<1><<<dim3(32, 128), 256>>>(bias + GG);
    lstm_seq<1><<<NBLK, NTHR, SMEM_SEQ2>>>(y, hf + BB * HH, cf + BB * HH);
}